// round 4
// baseline (speedup 1.0000x reference)
#include <cuda_runtime.h>

// ---------------------------------------------------------------------------
// SelfAttentionBlock: graph attention with per-edge RPE.
// N=50000, E=800000, DIM=256, H=16, D=8, DH=128, IN_RPE=18. SCALE=1/sqrt(8).
//
// Pipeline (4 kernels):
//   K0 init     : zero d_out, zero g_sum
//   K1 gemm     : g_qkv = x @ Wqkv + bqkv            (N, 512)
//   K2 compat   : per-edge RPE GEMVs + q.k dot, ex=exp(compat), atomicAdd den
//                 (no max subtraction: compat range << fp32 exp overflow)
//   K3 message  : out[s] += (ex/(den[s]+eps)) * v[t]  via red.global.v4.f32.add
// ---------------------------------------------------------------------------

#define MAX_N 50000
#define MAX_E 800000
#define HH    16
#define SCALE 0.35355339059327373f   // 8^-0.5

__device__ float g_qkv[(size_t)MAX_N * 512];   // [q(128) | k(128) | v(256)]
__device__ float g_ex [(size_t)MAX_E * HH];    // exp(compat)
__device__ float g_sum[(size_t)MAX_N * HH];    // softmax denominators

// Vectorized global reduction (sm_90+): one instruction adds 4 floats.
__device__ __forceinline__ void red_add_v4(float* addr, float a, float b,
                                           float c, float d) {
    asm volatile("red.global.v4.f32.add [%0], {%1, %2, %3, %4};"
                 :: "l"(addr), "f"(a), "f"(b), "f"(c), "f"(d)
                 : "memory");
}

// --------------------------- K0: init --------------------------------------
__global__ void k_init(float4* __restrict__ out, int n_out4, int n_nodes) {
    int i = blockIdx.x * blockDim.x + threadIdx.x;
    if (i < n_out4) out[i] = make_float4(0.f, 0.f, 0.f, 0.f);
    if (i < n_nodes * HH) g_sum[i] = 0.0f;
}

// --------------------------- K1: qkv GEMM ----------------------------------
// C[M,512] = X[M,256] @ W[256,512] + bias
// BM=128, BN=128, BK=16, TM=TN=8; double-buffered smem, reg-staged prefetch.
__global__ void __launch_bounds__(256) k_gemm(
    const float* __restrict__ X, const float* __restrict__ W,
    const float* __restrict__ bias, int M)
{
    __shared__ float As[2][16][128];   // transposed A tile: As[buf][k][row]
    __shared__ float Bs[2][16][128];   // Bs[buf][k][col]

    const int tid  = threadIdx.x;
    const int tr   = tid >> 4;          // 0..15
    const int tc   = tid & 15;          // 0..15
    const int aRow = tid >> 1;          // 0..127
    const int aCol = (tid & 1) * 8;     // 0 or 8
    const int bRow = tid >> 5;          // 0..7 (also +8)
    const int bCol = (tid & 31) * 4;    // 0..124

    const int rowBase = blockIdx.y * 128;
    const int colBase = blockIdx.x * 128;
    const int gRow = rowBase + aRow;
    const bool aOk = (gRow < M);
    const float* Xr = X + (size_t)gRow * 256;
    const float* Wc = W + colBase + bCol;

    float acc[8][8];
#pragma unroll
    for (int i = 0; i < 8; i++)
#pragma unroll
        for (int j = 0; j < 8; j++) acc[i][j] = 0.0f;

    // Prologue: load tile 0 into buffer 0
    float4 a0 = make_float4(0.f,0.f,0.f,0.f), a1 = a0, b0, b1;
    if (aOk) {
        a0 = *(const float4*)(Xr + aCol);
        a1 = *(const float4*)(Xr + aCol + 4);
    }
    b0 = *(const float4*)(Wc + (size_t)bRow * 512);
    b1 = *(const float4*)(Wc + (size_t)(bRow + 8) * 512);

    As[0][aCol+0][aRow]=a0.x; As[0][aCol+1][aRow]=a0.y;
    As[0][aCol+2][aRow]=a0.z; As[0][aCol+3][aRow]=a0.w;
    As[0][aCol+4][aRow]=a1.x; As[0][aCol+5][aRow]=a1.y;
    As[0][aCol+6][aRow]=a1.z; As[0][aCol+7][aRow]=a1.w;
    *(float4*)&Bs[0][bRow][bCol]   = b0;
    *(float4*)&Bs[0][bRow+8][bCol] = b1;
    __syncthreads();

    int cur = 0;
#pragma unroll
    for (int it = 0; it < 16; it++) {
        // Prefetch next tile into registers (latency hidden by compute)
        if (it < 15) {
            int k0 = (it + 1) * 16;
            a0 = make_float4(0.f,0.f,0.f,0.f); a1 = a0;
            if (aOk) {
                a0 = *(const float4*)(Xr + k0 + aCol);
                a1 = *(const float4*)(Xr + k0 + aCol + 4);
            }
            b0 = *(const float4*)(Wc + (size_t)(k0 + bRow) * 512);
            b1 = *(const float4*)(Wc + (size_t)(k0 + bRow + 8) * 512);
        }

#pragma unroll
        for (int k = 0; k < 16; k++) {
            float4 ra0 = *(float4*)&As[cur][k][tr * 8];
            float4 ra1 = *(float4*)&As[cur][k][tr * 8 + 4];
            float4 rb0 = *(float4*)&Bs[cur][k][tc * 8];
            float4 rb1 = *(float4*)&Bs[cur][k][tc * 8 + 4];
            float ra[8] = {ra0.x, ra0.y, ra0.z, ra0.w, ra1.x, ra1.y, ra1.z, ra1.w};
            float rb[8] = {rb0.x, rb0.y, rb0.z, rb0.w, rb1.x, rb1.y, rb1.z, rb1.w};
#pragma unroll
            for (int i = 0; i < 8; i++)
#pragma unroll
                for (int j = 0; j < 8; j++)
                    acc[i][j] += ra[i] * rb[j];
        }

        if (it < 15) {
            int nxt = cur ^ 1;
            As[nxt][aCol+0][aRow]=a0.x; As[nxt][aCol+1][aRow]=a0.y;
            As[nxt][aCol+2][aRow]=a0.z; As[nxt][aCol+3][aRow]=a0.w;
            As[nxt][aCol+4][aRow]=a1.x; As[nxt][aCol+5][aRow]=a1.y;
            As[nxt][aCol+6][aRow]=a1.z; As[nxt][aCol+7][aRow]=a1.w;
            *(float4*)&Bs[nxt][bRow][bCol]   = b0;
            *(float4*)&Bs[nxt][bRow+8][bCol] = b1;
            __syncthreads();
            cur = nxt;
        }
    }

#pragma unroll
    for (int i = 0; i < 8; i++) {
        int row = rowBase + tr * 8 + i;
        if (row < M) {
            int col = colBase + tc * 8;
            float4 c0 = *(const float4*)(bias + col);
            float4 c1 = *(const float4*)(bias + col + 4);
            float4 o0 = make_float4(acc[i][0] + c0.x, acc[i][1] + c0.y,
                                    acc[i][2] + c0.z, acc[i][3] + c0.w);
            float4 o1 = make_float4(acc[i][4] + c1.x, acc[i][5] + c1.y,
                                    acc[i][6] + c1.z, acc[i][7] + c1.w);
            *(float4*)(g_qkv + (size_t)row * 512 + col)     = o0;
            *(float4*)(g_qkv + (size_t)row * 512 + col + 4) = o1;
        }
    }
}

// --------------------------- K2: edge compat + exp + denom ------------------
// One warp per edge. Lane j handles dims [4j, 4j+4) of the 128-dim head space.
__global__ void __launch_bounds__(256) k_edge_compat(
    const int* __restrict__ ei, const float* __restrict__ ea,
    const float* __restrict__ Wk, const float* __restrict__ bk,
    const float* __restrict__ Wq, const float* __restrict__ bq, int E)
{
    __shared__ float sWq[18 * 128];
    __shared__ float sWk[18 * 128];
    __shared__ float sbq[128];
    __shared__ float sbk[128];

    for (int i = threadIdx.x; i < 18 * 128; i += 256) {
        sWq[i] = Wq[i];
        sWk[i] = Wk[i];
    }
    if (threadIdx.x < 128) {
        sbq[threadIdx.x] = bq[threadIdx.x];
        sbk[threadIdx.x] = bk[threadIdx.x];
    }
    __syncthreads();

    int e = blockIdx.x * 8 + (threadIdx.x >> 5);
    if (e >= E) return;
    int lane = threadIdx.x & 31;

    int s = ei[e];
    int t = ei[E + e];

    float eal = (lane < 18) ? ea[(size_t)e * 18 + lane] : 0.0f;

    const int c0 = lane * 4;
    float aq0 = sbq[c0], aq1 = sbq[c0 + 1], aq2 = sbq[c0 + 2], aq3 = sbq[c0 + 3];
    float ak0 = sbk[c0], ak1 = sbk[c0 + 1], ak2 = sbk[c0 + 2], ak3 = sbk[c0 + 3];

#pragma unroll
    for (int i = 0; i < 18; i++) {
        float v = __shfl_sync(0xffffffffu, eal, i);
        const float* wq = &sWq[i * 128 + c0];
        const float* wk = &sWk[i * 128 + c0];
        aq0 += v * wq[0]; aq1 += v * wq[1]; aq2 += v * wq[2]; aq3 += v * wq[3];
        ak0 += v * wk[0]; ak1 += v * wk[1]; ak2 += v * wk[2]; ak3 += v * wk[3];
    }

    float4 q4 = *(const float4*)(g_qkv + (size_t)s * 512 + c0);
    float4 k4 = *(const float4*)(g_qkv + (size_t)t * 512 + 128 + c0);

    float p = (q4.x * SCALE + aq0) * (k4.x + ak0)
            + (q4.y * SCALE + aq1) * (k4.y + ak1)
            + (q4.z * SCALE + aq2) * (k4.z + ak2)
            + (q4.w * SCALE + aq3) * (k4.w + ak3);
    p += __shfl_xor_sync(0xffffffffu, p, 1);

    if ((lane & 1) == 0) {
        int h = lane >> 1;
        float ex = __expf(p);          // safe: |compat| << 88
        g_ex[(size_t)e * HH + h] = ex;
        atomicAdd(&g_sum[s * HH + h], ex);
    }
}

// --------------------------- K3: weighted message scatter -------------------
// One warp per edge. Lane j handles out dims [8j, 8j+8) -> head j/2.
__global__ void __launch_bounds__(256) k_message(
    const int* __restrict__ ei, float* __restrict__ out, int E)
{
    int e = blockIdx.x * 8 + (threadIdx.x >> 5);
    if (e >= E) return;
    int lane = threadIdx.x & 31;

    int s = ei[e];
    int t = ei[E + e];
    int h = lane >> 1;

    float ex  = g_ex[(size_t)e * HH + h];
    float den = g_sum[s * HH + h];
    float a   = ex / (den + 1e-16f);

    const float* vp = g_qkv + (size_t)t * 512 + 256 + lane * 8;
    float4 v0 = *(const float4*)vp;
    float4 v1 = *(const float4*)(vp + 4);

    float* op = out + (size_t)s * 256 + lane * 8;
    red_add_v4(op,     a * v0.x, a * v0.y, a * v0.z, a * v0.w);
    red_add_v4(op + 4, a * v1.x, a * v1.y, a * v1.z, a * v1.w);
}

// ---------------------------------------------------------------------------
extern "C" void kernel_launch(void* const* d_in, const int* in_sizes, int n_in,
                              void* d_out, int out_size)
{
    const float* x    = (const float*)d_in[0];
    const int*   ei   = (const int*)d_in[1];
    const float* ea   = (const float*)d_in[2];
    const float* Wqkv = (const float*)d_in[3];
    const float* bqkv = (const float*)d_in[4];
    const float* Wk   = (const float*)d_in[5];
    const float* bk   = (const float*)d_in[6];
    const float* Wq   = (const float*)d_in[7];
    const float* bq   = (const float*)d_in[8];
    float*       out  = (float*)d_out;

    int M = in_sizes[0] / 256;   // num nodes
    int E = in_sizes[1] / 2;     // num edges

    int n_out4 = M * 64;   // M*256 floats / 4
    k_init<<<(n_out4 + 255) / 256, 256>>>((float4*)out, n_out4, M);

    dim3 g1(4, (M + 127) / 128);
    k_gemm<<<g1, 256>>>(x, Wqkv, bqkv, M);

    k_edge_compat<<<(E + 7) / 8, 256>>>(ei, ea, Wk, bk, Wq, bq, E);

    k_message<<<(E + 7) / 8, 256>>>(ei, out, E);
}

// round 5
// speedup vs baseline: 1.1871x; 1.1871x over previous
#include <cuda_runtime.h>

// ---------------------------------------------------------------------------
// SelfAttentionBlock: graph attention with per-edge RPE.
// N=50000, E=800000, DIM=256, H=16, D=8, DH=128, IN_RPE=18. SCALE=1/sqrt(8).
//
// Pipeline (4 kernels):
//   K0 init     : zero d_out, zero g_sum
//   K1 gemm     : g_qkv = x @ Wqkv + bqkv            (N, 512)
//   K2 compat   : per-edge RPE GEMVs + q.k dot, ex=exp(compat), atomicAdd den
//                 (no max subtraction: compat range << fp32 exp overflow)
//   K3 message  : out[s] += (ex/(den[s]+eps)) * v[t]  via red.global.v4.f32.add
// ---------------------------------------------------------------------------

#define MAX_N 50000
#define MAX_E 800000
#define HH    16
#define SCALE 0.35355339059327373f   // 8^-0.5

__device__ float g_qkv[(size_t)MAX_N * 512];   // [q(128) | k(128) | v(256)]
__device__ float g_ex [(size_t)MAX_E * HH];    // exp(compat)
__device__ float g_sum[(size_t)MAX_N * HH];    // softmax denominators

// Vectorized global reduction (sm_90+): one instruction adds 4 floats.
__device__ __forceinline__ void red_add_v4(float* addr, float a, float b,
                                           float c, float d) {
    asm volatile("red.global.v4.f32.add [%0], {%1, %2, %3, %4};"
                 :: "l"(addr), "f"(a), "f"(b), "f"(c), "f"(d)
                 : "memory");
}

// --------------------------- K0: init --------------------------------------
__global__ void k_init(float4* __restrict__ out, int n_out4, int n_nodes) {
    int i = blockIdx.x * blockDim.x + threadIdx.x;
    if (i < n_out4) out[i] = make_float4(0.f, 0.f, 0.f, 0.f);
    if (i < n_nodes * HH) g_sum[i] = 0.0f;
}

// --------------------------- K1: qkv GEMM ----------------------------------
// C[M,512] = X[M,256] @ W[256,512] + bias ;  BM=128, BN=128, BK=8, TM=TN=8
// (R3 version — known good; R4's aggressive unroll/double-buffer regressed.)
__global__ void __launch_bounds__(256) k_gemm(
    const float* __restrict__ X, const float* __restrict__ W,
    const float* __restrict__ bias, int M)
{
    __shared__ float As[8][128];   // transposed A tile
    __shared__ float Bs[8][128];

    const int tid = threadIdx.x;
    const int tr  = tid >> 4;          // 0..15
    const int tc  = tid & 15;          // 0..15
    const int aRow = tid >> 1;         // 0..127
    const int aCol = (tid & 1) * 4;    // 0 or 4
    const int bRow = tid >> 5;         // 0..7
    const int bCol = (tid & 31) * 4;   // 0..124

    const int rowBase = blockIdx.y * 128;
    const int colBase = blockIdx.x * 128;
    const int gRow = rowBase + aRow;

    float acc[8][8];
#pragma unroll
    for (int i = 0; i < 8; i++)
#pragma unroll
        for (int j = 0; j < 8; j++) acc[i][j] = 0.0f;

    for (int k0 = 0; k0 < 256; k0 += 8) {
        float4 a4 = make_float4(0.f, 0.f, 0.f, 0.f);
        if (gRow < M)
            a4 = *(const float4*)(X + (size_t)gRow * 256 + k0 + aCol);
        As[aCol + 0][aRow] = a4.x;
        As[aCol + 1][aRow] = a4.y;
        As[aCol + 2][aRow] = a4.z;
        As[aCol + 3][aRow] = a4.w;

        *(float4*)&Bs[bRow][bCol] =
            *(const float4*)(W + (size_t)(k0 + bRow) * 512 + colBase + bCol);
        __syncthreads();

#pragma unroll
        for (int k = 0; k < 8; k++) {
            float4 a0 = *(float4*)&As[k][tr * 8];
            float4 a1 = *(float4*)&As[k][tr * 8 + 4];
            float4 b0 = *(float4*)&Bs[k][tc * 8];
            float4 b1 = *(float4*)&Bs[k][tc * 8 + 4];
            float ra[8] = {a0.x, a0.y, a0.z, a0.w, a1.x, a1.y, a1.z, a1.w};
            float rb[8] = {b0.x, b0.y, b0.z, b0.w, b1.x, b1.y, b1.z, b1.w};
#pragma unroll
            for (int i = 0; i < 8; i++)
#pragma unroll
                for (int j = 0; j < 8; j++)
                    acc[i][j] += ra[i] * rb[j];
        }
        __syncthreads();
    }

#pragma unroll
    for (int i = 0; i < 8; i++) {
        int row = rowBase + tr * 8 + i;
        if (row < M) {
            int col = colBase + tc * 8;
            float4 b0 = *(const float4*)(bias + col);
            float4 b1 = *(const float4*)(bias + col + 4);
            float4 o0 = make_float4(acc[i][0] + b0.x, acc[i][1] + b0.y,
                                    acc[i][2] + b0.z, acc[i][3] + b0.w);
            float4 o1 = make_float4(acc[i][4] + b1.x, acc[i][5] + b1.y,
                                    acc[i][6] + b1.z, acc[i][7] + b1.w);
            *(float4*)(g_qkv + (size_t)row * 512 + col)     = o0;
            *(float4*)(g_qkv + (size_t)row * 512 + col + 4) = o1;
        }
    }
}

// --------------------------- K2: edge compat + exp + denom ------------------
// One warp per edge. Lane j handles dims [4j, 4j+4) of the 128-dim head space.
__global__ void __launch_bounds__(256) k_edge_compat(
    const int* __restrict__ ei, const float* __restrict__ ea,
    const float* __restrict__ Wk, const float* __restrict__ bk,
    const float* __restrict__ Wq, const float* __restrict__ bq, int E)
{
    __shared__ float sWq[18 * 128];
    __shared__ float sWk[18 * 128];
    __shared__ float sbq[128];
    __shared__ float sbk[128];

    for (int i = threadIdx.x; i < 18 * 128; i += 256) {
        sWq[i] = Wq[i];
        sWk[i] = Wk[i];
    }
    if (threadIdx.x < 128) {
        sbq[threadIdx.x] = bq[threadIdx.x];
        sbk[threadIdx.x] = bk[threadIdx.x];
    }
    __syncthreads();

    int e = blockIdx.x * 8 + (threadIdx.x >> 5);
    if (e >= E) return;
    int lane = threadIdx.x & 31;

    int s = ei[e];
    int t = ei[E + e];

    float eal = (lane < 18) ? ea[(size_t)e * 18 + lane] : 0.0f;

    const int c0 = lane * 4;
    float aq0 = sbq[c0], aq1 = sbq[c0 + 1], aq2 = sbq[c0 + 2], aq3 = sbq[c0 + 3];
    float ak0 = sbk[c0], ak1 = sbk[c0 + 1], ak2 = sbk[c0 + 2], ak3 = sbk[c0 + 3];

#pragma unroll
    for (int i = 0; i < 18; i++) {
        float v = __shfl_sync(0xffffffffu, eal, i);
        const float* wq = &sWq[i * 128 + c0];
        const float* wk = &sWk[i * 128 + c0];
        aq0 += v * wq[0]; aq1 += v * wq[1]; aq2 += v * wq[2]; aq3 += v * wq[3];
        ak0 += v * wk[0]; ak1 += v * wk[1]; ak2 += v * wk[2]; ak3 += v * wk[3];
    }

    float4 q4 = *(const float4*)(g_qkv + (size_t)s * 512 + c0);
    float4 k4 = *(const float4*)(g_qkv + (size_t)t * 512 + 128 + c0);

    float p = (q4.x * SCALE + aq0) * (k4.x + ak0)
            + (q4.y * SCALE + aq1) * (k4.y + ak1)
            + (q4.z * SCALE + aq2) * (k4.z + ak2)
            + (q4.w * SCALE + aq3) * (k4.w + ak3);
    p += __shfl_xor_sync(0xffffffffu, p, 1);

    if ((lane & 1) == 0) {
        int h = lane >> 1;
        float ex = __expf(p);          // safe: |compat| << 88
        g_ex[(size_t)e * HH + h] = ex;
        atomicAdd(&g_sum[s * HH + h], ex);
    }
}

// --------------------------- K3: weighted message scatter -------------------
// One warp per edge. Lane j handles out dims [8j, 8j+8) -> head j/2.
__global__ void __launch_bounds__(256) k_message(
    const int* __restrict__ ei, float* __restrict__ out, int E)
{
    int e = blockIdx.x * 8 + (threadIdx.x >> 5);
    if (e >= E) return;
    int lane = threadIdx.x & 31;

    int s = ei[e];
    int t = ei[E + e];
    int h = lane >> 1;

    float ex  = g_ex[(size_t)e * HH + h];
    float den = g_sum[s * HH + h];
    float a   = ex / (den + 1e-16f);

    const float* vp = g_qkv + (size_t)t * 512 + 256 + lane * 8;
    float4 v0 = *(const float4*)vp;
    float4 v1 = *(const float4*)(vp + 4);

    float* op = out + (size_t)s * 256 + lane * 8;
    red_add_v4(op,     a * v0.x, a * v0.y, a * v0.z, a * v0.w);
    red_add_v4(op + 4, a * v1.x, a * v1.y, a * v1.z, a * v1.w);
}

// ---------------------------------------------------------------------------
extern "C" void kernel_launch(void* const* d_in, const int* in_sizes, int n_in,
                              void* d_out, int out_size)
{
    const float* x    = (const float*)d_in[0];
    const int*   ei   = (const int*)d_in[1];
    const float* ea   = (const float*)d_in[2];
    const float* Wqkv = (const float*)d_in[3];
    const float* bqkv = (const float*)d_in[4];
    const float* Wk   = (const float*)d_in[5];
    const float* bk   = (const float*)d_in[6];
    const float* Wq   = (const float*)d_in[7];
    const float* bq   = (const float*)d_in[8];
    float*       out  = (float*)d_out;

    int M = in_sizes[0] / 256;   // num nodes
    int E = in_sizes[1] / 2;     // num edges

    int n_out4 = M * 64;   // M*256 floats / 4
    k_init<<<(n_out4 + 255) / 256, 256>>>((float4*)out, n_out4, M);

    dim3 g1(4, (M + 127) / 128);
    k_gemm<<<g1, 256>>>(x, Wqkv, bqkv, M);

    k_edge_compat<<<(E + 7) / 8, 256>>>(ei, ea, Wk, bk, Wq, bq, E);

    k_message<<<(E + 7) / 8, 256>>>(ei, out, E);
}

// round 6
// speedup vs baseline: 1.4352x; 1.2089x over previous
#include <cuda_runtime.h>
#include <cuda_bf16.h>

// ---------------------------------------------------------------------------
// SelfAttentionBlock: graph attention with per-edge RPE.
// N=50000, E=800000, DIM=256, H=16, D=8, DH=128, IN_RPE=18. SCALE=1/sqrt(8).
//
// Pipeline (6 kernels):
//   K0 init      : zero d_out, zero g_sum
//   K1a convert_x: x (fp32) -> xh + xl (bf16 split)
//   K1b convert_w: Wqkv (fp32) -> wht + wlt (bf16 split, transposed [n][k])
//   K1  gemm_mma : g_qkv = x @ Wqkv + bias via bf16x3 mma.sync (fp32 acc)
//   K2  compat   : per-edge RPE GEMVs + q.k dot, ex=exp(compat), atomicAdd den
//   K3  message  : out[s] += (ex/(den[s]+eps)) * v[t]  via red.global.v4.f32
// ---------------------------------------------------------------------------

#define MAX_N 50000
#define MAX_E 800000
#define HH    16
#define SCALE 0.35355339059327373f   // 8^-0.5

__device__ float g_qkv[(size_t)MAX_N * 512];   // [q(128) | k(128) | v(256)]
__device__ float g_ex [(size_t)MAX_E * HH];    // exp(compat)
__device__ float g_sum[(size_t)MAX_N * HH];    // softmax denominators

// bf16-split scratch for the tensor-core GEMM
__device__ __nv_bfloat16 g_xh[(size_t)MAX_N * 256];
__device__ __nv_bfloat16 g_xl[(size_t)MAX_N * 256];
__device__ __nv_bfloat16 g_wht[512 * 256];     // transposed: [n][k]
__device__ __nv_bfloat16 g_wlt[512 * 256];

// Vectorized global reduction (sm_90+): one instruction adds 4 floats.
__device__ __forceinline__ void red_add_v4(float* addr, float a, float b,
                                           float c, float d) {
    asm volatile("red.global.v4.f32.add [%0], {%1, %2, %3, %4};"
                 :: "l"(addr), "f"(a), "f"(b), "f"(c), "f"(d)
                 : "memory");
}

// cp.async 16B with zero-fill when srcBytes==0
__device__ __forceinline__ void cp_async_16(unsigned dst, const void* src,
                                            int srcBytes) {
    asm volatile("cp.async.cg.shared.global [%0], [%1], 16, %2;"
                 :: "r"(dst), "l"(src), "r"(srcBytes));
}

#define MMA16816(c, a0, a1, a2, a3, b0, b1)                                   \
    asm volatile("mma.sync.aligned.m16n8k16.row.col.f32.bf16.bf16.f32 "       \
                 "{%0,%1,%2,%3}, {%4,%5,%6,%7}, {%8,%9}, {%0,%1,%2,%3};"      \
                 : "+f"((c)[0]), "+f"((c)[1]), "+f"((c)[2]), "+f"((c)[3])     \
                 : "r"(a0), "r"(a1), "r"(a2), "r"(a3), "r"(b0), "r"(b1))

// --------------------------- K0: init --------------------------------------
__global__ void k_init(float4* __restrict__ out, int n_out4, int n_nodes) {
    int i = blockIdx.x * blockDim.x + threadIdx.x;
    if (i < n_out4) out[i] = make_float4(0.f, 0.f, 0.f, 0.f);
    if (i < n_nodes * HH) g_sum[i] = 0.0f;
}

// --------------------------- K1a: split-convert x ---------------------------
__global__ void k_convert_x(const float* __restrict__ x, int n) {
    int i = blockIdx.x * blockDim.x + threadIdx.x;
    if (i >= n) return;
    float v = x[i];
    __nv_bfloat16 h = __float2bfloat16(v);
    g_xh[i] = h;
    g_xl[i] = __float2bfloat16(v - __bfloat162float(h));
}

// --------------------------- K1b: split-convert + transpose W ---------------
__global__ void k_convert_w(const float* __restrict__ W) {
    int i = blockIdx.x * blockDim.x + threadIdx.x;   // i = k*512 + n
    if (i >= 256 * 512) return;
    int n = i & 511;
    int k = i >> 9;
    float v = W[i];
    __nv_bfloat16 h = __float2bfloat16(v);
    g_wht[n * 256 + k] = h;
    g_wlt[n * 256 + k] = __float2bfloat16(v - __bfloat162float(h));
}

// --------------------------- K1: bf16x3 tensor-core GEMM --------------------
// C[M,512] = X[M,256] @ W[256,512] + bias, via Xh*Wh + Xh*Wl + Xl*Wh.
// CTA tile 128x128, K chunk 32, 8 warps (2x4), warp tile 64x32.
// SMEM rows padded to 40 bf16 (80B): conflict-free frag loads, 16B-aligned
// for cp.async.
#define SMSTRIDE 40
__global__ void __launch_bounds__(256) k_gemm_mma(
    const float* __restrict__ bias, int M)
{
    __shared__ __nv_bfloat16 Ah[128 * SMSTRIDE];
    __shared__ __nv_bfloat16 Al[128 * SMSTRIDE];
    __shared__ __nv_bfloat16 Bh[128 * SMSTRIDE];
    __shared__ __nv_bfloat16 Bl[128 * SMSTRIDE];

    const int tid  = threadIdx.x;
    const int wid  = tid >> 5;
    const int lane = tid & 31;
    const int g    = lane >> 2;       // group id 0..7
    const int tg   = lane & 3;        // thread in group
    const int wm   = wid >> 2;        // 0..1
    const int wn   = wid & 3;         // 0..3

    const int rowTile = blockIdx.y * 128;
    const int colTile = blockIdx.x * 128;

    const unsigned AhU = (unsigned)__cvta_generic_to_shared(Ah);
    const unsigned AlU = (unsigned)__cvta_generic_to_shared(Al);
    const unsigned BhU = (unsigned)__cvta_generic_to_shared(Bh);
    const unsigned BlU = (unsigned)__cvta_generic_to_shared(Bl);

    float acc[4][4][4];
#pragma unroll
    for (int mf = 0; mf < 4; mf++)
#pragma unroll
        for (int nf = 0; nf < 4; nf++)
#pragma unroll
            for (int r = 0; r < 4; r++) acc[mf][nf][r] = 0.0f;

#pragma unroll 1
    for (int kt = 0; kt < 8; kt++) {
        const int k0 = kt * 32;
        // Stage tiles: 512 16B-chunks per tile, 2 per thread per tile.
#pragma unroll
        for (int j = 0; j < 2; j++) {
            int c   = tid + j * 256;     // 0..511
            int r   = c >> 2;            // row 0..127
            int off = c & 3;             // 16B chunk within 64B row-slice
            unsigned soff = (unsigned)(r * SMSTRIDE * 2 + off * 16);

            int rowG = rowTile + r;
            int nb   = (rowG < M) ? 16 : 0;
            const __nv_bfloat16* sa =
                g_xh + (size_t)rowG * 256 + k0 + off * 8;
            const __nv_bfloat16* sal =
                g_xl + (size_t)rowG * 256 + k0 + off * 8;
            cp_async_16(AhU + soff, sa, nb);
            cp_async_16(AlU + soff, sal, nb);

            int nG = colTile + r;
            cp_async_16(BhU + soff, g_wht + (size_t)nG * 256 + k0 + off * 8, 16);
            cp_async_16(BlU + soff, g_wlt + (size_t)nG * 256 + k0 + off * 8, 16);
        }
        asm volatile("cp.async.commit_group;");
        asm volatile("cp.async.wait_group 0;");
        __syncthreads();

#pragma unroll
        for (int ks = 0; ks < 2; ks++) {
            const int kc = ks * 16 + tg * 2;

            unsigned bh[4][2], bl[4][2];
#pragma unroll
            for (int nf = 0; nf < 4; nf++) {
                int nb0 = (wn * 32 + nf * 8 + g) * SMSTRIDE;
                bh[nf][0] = *(const unsigned*)&Bh[nb0 + kc];
                bh[nf][1] = *(const unsigned*)&Bh[nb0 + kc + 8];
                bl[nf][0] = *(const unsigned*)&Bl[nb0 + kc];
                bl[nf][1] = *(const unsigned*)&Bl[nb0 + kc + 8];
            }
#pragma unroll
            for (int mf = 0; mf < 4; mf++) {
                int r0 = (wm * 64 + mf * 16 + g) * SMSTRIDE;
                int r8 = r0 + 8 * SMSTRIDE;
                unsigned ah0 = *(const unsigned*)&Ah[r0 + kc];
                unsigned ah1 = *(const unsigned*)&Ah[r8 + kc];
                unsigned ah2 = *(const unsigned*)&Ah[r0 + kc + 8];
                unsigned ah3 = *(const unsigned*)&Ah[r8 + kc + 8];
                unsigned al0 = *(const unsigned*)&Al[r0 + kc];
                unsigned al1 = *(const unsigned*)&Al[r8 + kc];
                unsigned al2 = *(const unsigned*)&Al[r0 + kc + 8];
                unsigned al3 = *(const unsigned*)&Al[r8 + kc + 8];
#pragma unroll
                for (int nf = 0; nf < 4; nf++) {
                    MMA16816(acc[mf][nf], ah0, ah1, ah2, ah3,
                             bh[nf][0], bh[nf][1]);
                    MMA16816(acc[mf][nf], ah0, ah1, ah2, ah3,
                             bl[nf][0], bl[nf][1]);
                    MMA16816(acc[mf][nf], al0, al1, al2, al3,
                             bh[nf][0], bh[nf][1]);
                }
            }
        }
        __syncthreads();
    }

    // Epilogue: bias + store. c0,c1 = (row g, cols tg*2,+1); c2,c3 = row g+8.
#pragma unroll
    for (int mf = 0; mf < 4; mf++) {
        int row0 = rowTile + wm * 64 + mf * 16 + g;
        int row1 = row0 + 8;
#pragma unroll
        for (int nf = 0; nf < 4; nf++) {
            int col = colTile + wn * 32 + nf * 8 + tg * 2;
            float2 bb = *(const float2*)(bias + col);
            if (row0 < M) {
                float2 o = make_float2(acc[mf][nf][0] + bb.x,
                                       acc[mf][nf][1] + bb.y);
                *(float2*)(g_qkv + (size_t)row0 * 512 + col) = o;
            }
            if (row1 < M) {
                float2 o = make_float2(acc[mf][nf][2] + bb.x,
                                       acc[mf][nf][3] + bb.y);
                *(float2*)(g_qkv + (size_t)row1 * 512 + col) = o;
            }
        }
    }
}

// --------------------------- K2: edge compat + exp + denom ------------------
// One warp per edge. Lane j handles dims [4j, 4j+4) of the 128-dim head space.
__global__ void __launch_bounds__(256) k_edge_compat(
    const int* __restrict__ ei, const float* __restrict__ ea,
    const float* __restrict__ Wk, const float* __restrict__ bk,
    const float* __restrict__ Wq, const float* __restrict__ bq, int E)
{
    __shared__ float sWq[18 * 128];
    __shared__ float sWk[18 * 128];
    __shared__ float sbq[128];
    __shared__ float sbk[128];

    for (int i = threadIdx.x; i < 18 * 128; i += 256) {
        sWq[i] = Wq[i];
        sWk[i] = Wk[i];
    }
    if (threadIdx.x < 128) {
        sbq[threadIdx.x] = bq[threadIdx.x];
        sbk[threadIdx.x] = bk[threadIdx.x];
    }
    __syncthreads();

    int e = blockIdx.x * 8 + (threadIdx.x >> 5);
    if (e >= E) return;
    int lane = threadIdx.x & 31;

    int s = ei[e];
    int t = ei[E + e];

    float eal = (lane < 18) ? ea[(size_t)e * 18 + lane] : 0.0f;

    const int c0 = lane * 4;
    float aq0 = sbq[c0], aq1 = sbq[c0 + 1], aq2 = sbq[c0 + 2], aq3 = sbq[c0 + 3];
    float ak0 = sbk[c0], ak1 = sbk[c0 + 1], ak2 = sbk[c0 + 2], ak3 = sbk[c0 + 3];

#pragma unroll
    for (int i = 0; i < 18; i++) {
        float v = __shfl_sync(0xffffffffu, eal, i);
        const float* wq = &sWq[i * 128 + c0];
        const float* wk = &sWk[i * 128 + c0];
        aq0 += v * wq[0]; aq1 += v * wq[1]; aq2 += v * wq[2]; aq3 += v * wq[3];
        ak0 += v * wk[0]; ak1 += v * wk[1]; ak2 += v * wk[2]; ak3 += v * wk[3];
    }

    float4 q4 = *(const float4*)(g_qkv + (size_t)s * 512 + c0);
    float4 k4 = *(const float4*)(g_qkv + (size_t)t * 512 + 128 + c0);

    float p = (q4.x * SCALE + aq0) * (k4.x + ak0)
            + (q4.y * SCALE + aq1) * (k4.y + ak1)
            + (q4.z * SCALE + aq2) * (k4.z + ak2)
            + (q4.w * SCALE + aq3) * (k4.w + ak3);
    p += __shfl_xor_sync(0xffffffffu, p, 1);

    if ((lane & 1) == 0) {
        int h = lane >> 1;
        float ex = __expf(p);          // safe: |compat| << 88
        g_ex[(size_t)e * HH + h] = ex;
        atomicAdd(&g_sum[s * HH + h], ex);
    }
}

// --------------------------- K3: weighted message scatter -------------------
// One warp per edge. Lane j handles out dims [8j, 8j+8) -> head j/2.
__global__ void __launch_bounds__(256) k_message(
    const int* __restrict__ ei, float* __restrict__ out, int E)
{
    int e = blockIdx.x * 8 + (threadIdx.x >> 5);
    if (e >= E) return;
    int lane = threadIdx.x & 31;

    int s = ei[e];
    int t = ei[E + e];
    int h = lane >> 1;

    float ex  = g_ex[(size_t)e * HH + h];
    float den = g_sum[s * HH + h];
    float a   = ex / (den + 1e-16f);

    const float* vp = g_qkv + (size_t)t * 512 + 256 + lane * 8;
    float4 v0 = *(const float4*)vp;
    float4 v1 = *(const float4*)(vp + 4);

    float* op = out + (size_t)s * 256 + lane * 8;
    red_add_v4(op,     a * v0.x, a * v0.y, a * v0.z, a * v0.w);
    red_add_v4(op + 4, a * v1.x, a * v1.y, a * v1.z, a * v1.w);
}

// ---------------------------------------------------------------------------
extern "C" void kernel_launch(void* const* d_in, const int* in_sizes, int n_in,
                              void* d_out, int out_size)
{
    const float* x    = (const float*)d_in[0];
    const int*   ei   = (const int*)d_in[1];
    const float* ea   = (const float*)d_in[2];
    const float* Wqkv = (const float*)d_in[3];
    const float* bqkv = (const float*)d_in[4];
    const float* Wk   = (const float*)d_in[5];
    const float* bk   = (const float*)d_in[6];
    const float* Wq   = (const float*)d_in[7];
    const float* bq   = (const float*)d_in[8];
    float*       out  = (float*)d_out;

    int M = in_sizes[0] / 256;   // num nodes
    int E = in_sizes[1] / 2;     // num edges

    int n_out4 = M * 64;   // M*256 floats / 4
    k_init<<<(n_out4 + 255) / 256, 256>>>((float4*)out, n_out4, M);

    int nx = M * 256;
    k_convert_x<<<(nx + 255) / 256, 256>>>(x, nx);
    k_convert_w<<<(256 * 512 + 255) / 256, 256>>>(Wqkv);

    dim3 g1(4, (M + 127) / 128);
    k_gemm_mma<<<g1, 256>>>(bqkv, M);

    k_edge_compat<<<(E + 7) / 8, 256>>>(ei, ea, Wk, bk, Wq, bq, E);

    k_message<<<(E + 7) / 8, 256>>>(ei, out, E);
}

// round 7
// speedup vs baseline: 1.5613x; 1.0879x over previous
#include <cuda_runtime.h>
#include <cuda_bf16.h>

// ---------------------------------------------------------------------------
// SelfAttentionBlock: graph attention with per-edge RPE.
// N=50000, E=800000, DIM=256, H=16, D=8, DH=128, IN_RPE=18. SCALE=1/sqrt(8).
//
// Pipeline (6 kernels):
//   K0 init      : zero d_out, zero g_sum
//   K1a convert_x: x (fp32) -> xh + xl (bf16 split)
//   K1b convert_w: Wqkv (fp32) -> wht + wlt (bf16 split, transposed [n][k])
//   K1  gemm_mma : g_qkv = x @ Wqkv + bias via bf16x3 mma.sync (fp32 acc)
//   K2  compat   : persistent warps, RPE weights in REGISTERS (no smem),
//                  2 warps per edge (64 dims each), exp + atomicAdd denom
//   K3  message  : out[s] += (ex/(den[s]+eps)) * v[t]  via red.global.v4.f32
// ---------------------------------------------------------------------------

#define MAX_N 50000
#define MAX_E 800000
#define HH    16
#define SCALE 0.35355339059327373f   // 8^-0.5

__device__ float g_qkv[(size_t)MAX_N * 512];   // [q(128) | k(128) | v(256)]
__device__ float g_ex [(size_t)MAX_E * HH];    // exp(compat)
__device__ float g_sum[(size_t)MAX_N * HH];    // softmax denominators

// bf16-split scratch for the tensor-core GEMM
__device__ __nv_bfloat16 g_xh[(size_t)MAX_N * 256];
__device__ __nv_bfloat16 g_xl[(size_t)MAX_N * 256];
__device__ __nv_bfloat16 g_wht[512 * 256];     // transposed: [n][k]
__device__ __nv_bfloat16 g_wlt[512 * 256];

// Vectorized global reduction (sm_90+): one instruction adds 4 floats.
__device__ __forceinline__ void red_add_v4(float* addr, float a, float b,
                                           float c, float d) {
    asm volatile("red.global.v4.f32.add [%0], {%1, %2, %3, %4};"
                 :: "l"(addr), "f"(a), "f"(b), "f"(c), "f"(d)
                 : "memory");
}

// cp.async 16B with zero-fill when srcBytes==0
__device__ __forceinline__ void cp_async_16(unsigned dst, const void* src,
                                            int srcBytes) {
    asm volatile("cp.async.cg.shared.global [%0], [%1], 16, %2;"
                 :: "r"(dst), "l"(src), "r"(srcBytes));
}

#define MMA16816(c, a0, a1, a2, a3, b0, b1)                                   \
    asm volatile("mma.sync.aligned.m16n8k16.row.col.f32.bf16.bf16.f32 "       \
                 "{%0,%1,%2,%3}, {%4,%5,%6,%7}, {%8,%9}, {%0,%1,%2,%3};"      \
                 : "+f"((c)[0]), "+f"((c)[1]), "+f"((c)[2]), "+f"((c)[3])     \
                 : "r"(a0), "r"(a1), "r"(a2), "r"(a3), "r"(b0), "r"(b1))

// --------------------------- K0: init --------------------------------------
__global__ void k_init(float4* __restrict__ out, int n_out4, int n_nodes) {
    int i = blockIdx.x * blockDim.x + threadIdx.x;
    if (i < n_out4) out[i] = make_float4(0.f, 0.f, 0.f, 0.f);
    if (i < n_nodes * HH) g_sum[i] = 0.0f;
}

// --------------------------- K1a: split-convert x ---------------------------
__global__ void k_convert_x(const float* __restrict__ x, int n) {
    int i = blockIdx.x * blockDim.x + threadIdx.x;
    if (i >= n) return;
    float v = x[i];
    __nv_bfloat16 h = __float2bfloat16(v);
    g_xh[i] = h;
    g_xl[i] = __float2bfloat16(v - __bfloat162float(h));
}

// --------------------------- K1b: split-convert + transpose W ---------------
__global__ void k_convert_w(const float* __restrict__ W) {
    int i = blockIdx.x * blockDim.x + threadIdx.x;   // i = k*512 + n
    if (i >= 256 * 512) return;
    int n = i & 511;
    int k = i >> 9;
    float v = W[i];
    __nv_bfloat16 h = __float2bfloat16(v);
    g_wht[n * 256 + k] = h;
    g_wlt[n * 256 + k] = __float2bfloat16(v - __bfloat162float(h));
}

// --------------------------- K1: bf16x3 tensor-core GEMM --------------------
// C[M,512] = X[M,256] @ W[256,512] + bias, via Xh*Wh + Xh*Wl + Xl*Wh.
// CTA tile 128x128, K chunk 32, 8 warps (2x4), warp tile 64x32.
#define SMSTRIDE 40
__global__ void __launch_bounds__(256) k_gemm_mma(
    const float* __restrict__ bias, int M)
{
    __shared__ __nv_bfloat16 Ah[128 * SMSTRIDE];
    __shared__ __nv_bfloat16 Al[128 * SMSTRIDE];
    __shared__ __nv_bfloat16 Bh[128 * SMSTRIDE];
    __shared__ __nv_bfloat16 Bl[128 * SMSTRIDE];

    const int tid  = threadIdx.x;
    const int wid  = tid >> 5;
    const int lane = tid & 31;
    const int g    = lane >> 2;       // group id 0..7
    const int tg   = lane & 3;        // thread in group
    const int wm   = wid >> 2;        // 0..1
    const int wn   = wid & 3;         // 0..3

    const int rowTile = blockIdx.y * 128;
    const int colTile = blockIdx.x * 128;

    const unsigned AhU = (unsigned)__cvta_generic_to_shared(Ah);
    const unsigned AlU = (unsigned)__cvta_generic_to_shared(Al);
    const unsigned BhU = (unsigned)__cvta_generic_to_shared(Bh);
    const unsigned BlU = (unsigned)__cvta_generic_to_shared(Bl);

    float acc[4][4][4];
#pragma unroll
    for (int mf = 0; mf < 4; mf++)
#pragma unroll
        for (int nf = 0; nf < 4; nf++)
#pragma unroll
            for (int r = 0; r < 4; r++) acc[mf][nf][r] = 0.0f;

#pragma unroll 1
    for (int kt = 0; kt < 8; kt++) {
        const int k0 = kt * 32;
#pragma unroll
        for (int j = 0; j < 2; j++) {
            int c   = tid + j * 256;     // 0..511
            int r   = c >> 2;            // row 0..127
            int off = c & 3;             // 16B chunk within 64B row-slice
            unsigned soff = (unsigned)(r * SMSTRIDE * 2 + off * 16);

            int rowG = rowTile + r;
            int nb   = (rowG < M) ? 16 : 0;
            cp_async_16(AhU + soff, g_xh + (size_t)rowG * 256 + k0 + off * 8, nb);
            cp_async_16(AlU + soff, g_xl + (size_t)rowG * 256 + k0 + off * 8, nb);

            int nG = colTile + r;
            cp_async_16(BhU + soff, g_wht + (size_t)nG * 256 + k0 + off * 8, 16);
            cp_async_16(BlU + soff, g_wlt + (size_t)nG * 256 + k0 + off * 8, 16);
        }
        asm volatile("cp.async.commit_group;");
        asm volatile("cp.async.wait_group 0;");
        __syncthreads();

#pragma unroll
        for (int ks = 0; ks < 2; ks++) {
            const int kc = ks * 16 + tg * 2;

            unsigned bh[4][2], bl[4][2];
#pragma unroll
            for (int nf = 0; nf < 4; nf++) {
                int nb0 = (wn * 32 + nf * 8 + g) * SMSTRIDE;
                bh[nf][0] = *(const unsigned*)&Bh[nb0 + kc];
                bh[nf][1] = *(const unsigned*)&Bh[nb0 + kc + 8];
                bl[nf][0] = *(const unsigned*)&Bl[nb0 + kc];
                bl[nf][1] = *(const unsigned*)&Bl[nb0 + kc + 8];
            }
#pragma unroll
            for (int mf = 0; mf < 4; mf++) {
                int r0 = (wm * 64 + mf * 16 + g) * SMSTRIDE;
                int r8 = r0 + 8 * SMSTRIDE;
                unsigned ah0 = *(const unsigned*)&Ah[r0 + kc];
                unsigned ah1 = *(const unsigned*)&Ah[r8 + kc];
                unsigned ah2 = *(const unsigned*)&Ah[r0 + kc + 8];
                unsigned ah3 = *(const unsigned*)&Ah[r8 + kc + 8];
                unsigned al0 = *(const unsigned*)&Al[r0 + kc];
                unsigned al1 = *(const unsigned*)&Al[r8 + kc];
                unsigned al2 = *(const unsigned*)&Al[r0 + kc + 8];
                unsigned al3 = *(const unsigned*)&Al[r8 + kc + 8];
#pragma unroll
                for (int nf = 0; nf < 4; nf++) {
                    MMA16816(acc[mf][nf], ah0, ah1, ah2, ah3,
                             bh[nf][0], bh[nf][1]);
                    MMA16816(acc[mf][nf], ah0, ah1, ah2, ah3,
                             bl[nf][0], bl[nf][1]);
                    MMA16816(acc[mf][nf], al0, al1, al2, al3,
                             bh[nf][0], bh[nf][1]);
                }
            }
        }
        __syncthreads();
    }

#pragma unroll
    for (int mf = 0; mf < 4; mf++) {
        int row0 = rowTile + wm * 64 + mf * 16 + g;
        int row1 = row0 + 8;
#pragma unroll
        for (int nf = 0; nf < 4; nf++) {
            int col = colTile + wn * 32 + nf * 8 + tg * 2;
            float2 bb = *(const float2*)(bias + col);
            if (row0 < M) {
                float2 o = make_float2(acc[mf][nf][0] + bb.x,
                                       acc[mf][nf][1] + bb.y);
                *(float2*)(g_qkv + (size_t)row0 * 512 + col) = o;
            }
            if (row1 < M) {
                float2 o = make_float2(acc[mf][nf][2] + bb.x,
                                       acc[mf][nf][3] + bb.y);
                *(float2*)(g_qkv + (size_t)row1 * 512 + col) = o;
            }
        }
    }
}

// --------------------------- K2: edge compat (register weights) -------------
// Persistent grid-stride warps. Each warp owns a fixed 64-dim half of the
// 128-dim head space (parity: 0 -> dims 0..63 / heads 0..7, 1 -> 64..127 /
// heads 8..15). Lane owns 2 dims; RPE weights live in 72 registers/lane,
// loaded once. No shared memory in the edge loop.
__global__ void __launch_bounds__(256, 2) k_edge_compat(
    const int* __restrict__ ei, const float* __restrict__ ea,
    const float* __restrict__ Wk, const float* __restrict__ bk,
    const float* __restrict__ Wq, const float* __restrict__ bq, int E)
{
    const int gwid   = (blockIdx.x * blockDim.x + threadIdx.x) >> 5;
    const int lane   = threadIdx.x & 31;
    const int parity = gwid & 1;
    const int c      = parity * 64 + lane * 2;   // dim pair owned by this lane

    // Load RPE weights into registers (once per warp lifetime).
    float wq0[18], wq1[18], wk0[18], wk1[18];
#pragma unroll
    for (int i = 0; i < 18; i++) {
        float2 t = *(const float2*)(Wq + i * 128 + c);
        wq0[i] = t.x; wq1[i] = t.y;
        float2 u = *(const float2*)(Wk + i * 128 + c);
        wk0[i] = u.x; wk1[i] = u.y;
    }
    const float2 bqv = *(const float2*)(bq + c);
    const float2 bkv = *(const float2*)(bk + c);
    const int h = parity * 8 + (lane >> 2);      // head written by lead lanes

    const int nWarps = (gridDim.x * blockDim.x) >> 5;
    const int stride = nWarps >> 1;

    for (int e = gwid >> 1; e < E; e += stride) {
        int s = ei[e];
        int t = ei[E + e];
        float eal = (lane < 18) ? ea[(size_t)e * 18 + lane] : 0.0f;

        float aq0 = bqv.x, aq1 = bqv.y;
        float ak0 = bkv.x, ak1 = bkv.y;
#pragma unroll
        for (int i = 0; i < 18; i++) {
            float v = __shfl_sync(0xffffffffu, eal, i);
            aq0 += v * wq0[i]; aq1 += v * wq1[i];
            ak0 += v * wk0[i]; ak1 += v * wk1[i];
        }

        float2 q2 = *(const float2*)(g_qkv + (size_t)s * 512 + c);
        float2 k2 = *(const float2*)(g_qkv + (size_t)t * 512 + 128 + c);

        float p = (q2.x * SCALE + aq0) * (k2.x + ak0)
                + (q2.y * SCALE + aq1) * (k2.y + ak1);
        p += __shfl_xor_sync(0xffffffffu, p, 1);
        p += __shfl_xor_sync(0xffffffffu, p, 2);

        if ((lane & 3) == 0) {
            float ex = __expf(p);          // safe: |compat| << 88
            g_ex[(size_t)e * HH + h] = ex;
            atomicAdd(&g_sum[s * HH + h], ex);
        }
    }
}

// --------------------------- K3: weighted message scatter -------------------
// One warp per edge. Lane j handles out dims [8j, 8j+8) -> head j/2.
__global__ void __launch_bounds__(256) k_message(
    const int* __restrict__ ei, float* __restrict__ out, int E)
{
    int e = blockIdx.x * 8 + (threadIdx.x >> 5);
    if (e >= E) return;
    int lane = threadIdx.x & 31;

    int s = ei[e];
    int t = ei[E + e];
    int h = lane >> 1;

    float ex  = g_ex[(size_t)e * HH + h];
    float den = g_sum[s * HH + h];
    float a   = ex / (den + 1e-16f);

    const float* vp = g_qkv + (size_t)t * 512 + 256 + lane * 8;
    float4 v0 = *(const float4*)vp;
    float4 v1 = *(const float4*)(vp + 4);

    float* op = out + (size_t)s * 256 + lane * 8;
    red_add_v4(op,     a * v0.x, a * v0.y, a * v0.z, a * v0.w);
    red_add_v4(op + 4, a * v1.x, a * v1.y, a * v1.z, a * v1.w);
}

// ---------------------------------------------------------------------------
extern "C" void kernel_launch(void* const* d_in, const int* in_sizes, int n_in,
                              void* d_out, int out_size)
{
    const float* x    = (const float*)d_in[0];
    const int*   ei   = (const int*)d_in[1];
    const float* ea   = (const float*)d_in[2];
    const float* Wqkv = (const float*)d_in[3];
    const float* bqkv = (const float*)d_in[4];
    const float* Wk   = (const float*)d_in[5];
    const float* bk   = (const float*)d_in[6];
    const float* Wq   = (const float*)d_in[7];
    const float* bq   = (const float*)d_in[8];
    float*       out  = (float*)d_out;

    int M = in_sizes[0] / 256;   // num nodes
    int E = in_sizes[1] / 2;     // num edges

    int n_out4 = M * 64;   // M*256 floats / 4
    k_init<<<(n_out4 + 255) / 256, 256>>>((float4*)out, n_out4, M);

    int nx = M * 256;
    k_convert_x<<<(nx + 255) / 256, 256>>>(x, nx);
    k_convert_w<<<(256 * 512 + 255) / 256, 256>>>(Wqkv);

    dim3 g1(4, (M + 127) / 128);
    k_gemm_mma<<<g1, 256>>>(bqkv, M);

    // Persistent grid-stride: 1184 blocks (8 warps each), 2 warps per edge.
    k_edge_compat<<<1184, 256>>>(ei, ea, Wk, bk, Wq, bq, E);

    k_message<<<(E + 7) / 8, 256>>>(ei, out, E);
}